// round 1
// baseline (speedup 1.0000x reference)
#include <cuda_runtime.h>
#include <math.h>

#define NPTS 131072
#define NC 4096

// ---------------- scratch (device globals: no allocation allowed) ----------
__device__ int g_cell_of[NPTS];
__device__ int g_sorted[NPTS];
__device__ int g_count[NC];
__device__ int g_start[NC];
__device__ int g_cursor[NC];

// ---------------- pass 0: zero counters ------------------------------------
__global__ void k_zero() {
    int t = blockIdx.x * blockDim.x + threadIdx.x;
    if (t < NC) { g_count[t] = 0; g_cursor[t] = 0; }
}

__device__ __forceinline__ int cell_coord(float v) {
    // match jnp: clip((x / (SCALE/N) + N/2).astype(int32), 0, N-1)
    // SCALE/N = 0.1875 exact; astype truncates toward zero, as does (int) cast.
    float f = v / 0.1875f + 8.0f;
    int c = (int)f;
    if (c < 0) c = 0;
    if (c > 15) c = 15;
    return c;
}

// ---------------- pass 1: cell index + histogram ----------------------------
__global__ void k_hist(const float* __restrict__ x) {
    int p = blockIdx.x * blockDim.x + threadIdx.x;
    if (p >= NPTS) return;
    int c0 = cell_coord(x[3 * p + 0]);
    int c1 = cell_coord(x[3 * p + 1]);
    int c2 = cell_coord(x[3 * p + 2]);
    int cell = (c0 * 16 + c1) * 16 + c2;
    g_cell_of[p] = cell;
    atomicAdd(&g_count[cell], 1);
}

// ---------------- pass 2: exclusive scan over 4096 counts (1 block) --------
__global__ void k_scan() {
    __shared__ int s[1024];
    int t = threadIdx.x;           // launched with 1024 threads
    int b = t * 4;
    int c0 = g_count[b + 0];
    int c1 = g_count[b + 1];
    int c2 = g_count[b + 2];
    int c3 = g_count[b + 3];
    int sum = c0 + c1 + c2 + c3;
    s[t] = sum;
    __syncthreads();
    #pragma unroll
    for (int off = 1; off < 1024; off <<= 1) {
        int v = (t >= off) ? s[t - off] : 0;
        __syncthreads();
        s[t] += v;
        __syncthreads();
    }
    int excl = s[t] - sum;
    g_start[b + 0] = excl;
    g_start[b + 1] = excl + c0;
    g_start[b + 2] = excl + c0 + c1;
    g_start[b + 3] = excl + c0 + c1 + c2;
}

// ---------------- pass 3: scatter point indices into cell buckets ----------
__global__ void k_scatter() {
    int p = blockIdx.x * blockDim.x + threadIdx.x;
    if (p >= NPTS) return;
    int cell = g_cell_of[p];
    int pos = g_start[cell] + atomicAdd(&g_cursor[cell], 1);
    g_sorted[pos] = p;
}

// ---------------- pass 4: per-cell MLP with weights in shared memory -------
template <int NO>
__device__ __forceinline__ void feed(float v, const float* __restrict__ w,
                                     float* acc) {
    #pragma unroll
    for (int o = 0; o < NO; o++) acc[o] = fmaf(v, w[o], acc[o]);
}

__global__ void __launch_bounds__(64) k_mlp(
    const float* __restrict__ x, const float* __restrict__ d,
    const float* __restrict__ w1, const float* __restrict__ b1,
    const float* __restrict__ w2, const float* __restrict__ b2,
    const float* __restrict__ w3, const float* __restrict__ b3,
    const float* __restrict__ w4, const float* __restrict__ b4,
    const float* __restrict__ w5, const float* __restrict__ b5,
    float* __restrict__ out)
{
    int cell = blockIdx.x;
    int cnt = g_count[cell];
    if (cnt == 0) return;

    __shared__ __align__(16) float sw1[2016];  // 63 x 32
    __shared__ __align__(16) float sb1[32];
    __shared__ __align__(16) float sw2[1056];  // 32 x 33
    __shared__ __align__(16) float sb2[36];    // 33 used (padded)
    __shared__ __align__(16) float sw3[1024];  // 32 x 32
    __shared__ __align__(16) float sb3[32];
    __shared__ __align__(16) float sw4[1888];  // 59 x 32
    __shared__ __align__(16) float sb4[32];
    __shared__ __align__(16) float sw5[96];    // 32 x 3
    __shared__ __align__(16) float sb5[4];     // 3 used

    {
        int tid = threadIdx.x;
        const size_t c = (size_t)cell;
        for (int i = tid; i < 2016; i += 64) sw1[i] = w1[c * 2016 + i];
        for (int i = tid; i < 32;   i += 64) sb1[i] = b1[c * 32 + i];
        for (int i = tid; i < 1056; i += 64) sw2[i] = w2[c * 1056 + i];
        for (int i = tid; i < 33;   i += 64) sb2[i] = b2[c * 33 + i];
        for (int i = tid; i < 1024; i += 64) sw3[i] = w3[c * 1024 + i];
        for (int i = tid; i < 32;   i += 64) sb3[i] = b3[c * 32 + i];
        for (int i = tid; i < 1888; i += 64) sw4[i] = w4[c * 1888 + i];
        for (int i = tid; i < 32;   i += 64) sb4[i] = b4[c * 32 + i];
        for (int i = tid; i < 96;   i += 64) sw5[i] = w5[c * 96 + i];
        for (int i = tid; i < 3;    i += 64) sb5[i] = b5[c * 3 + i];
    }
    __syncthreads();

    int start = g_start[cell];
    for (int q = threadIdx.x; q < cnt; q += 64) {
        int idx = g_sorted[start + q];
        float x0 = x[3 * idx + 0], x1 = x[3 * idx + 1], x2 = x[3 * idx + 2];
        float d0 = d[3 * idx + 0], d1 = d[3 * idx + 1], d2 = d[3 * idx + 2];
        bool mask = (fabsf(x0) < 1.5f) && (fabsf(x1) < 1.5f) && (fabsf(x2) < 1.5f);

        float A[33], B[33];

        // ---- layer 1: encode(x) [63] -> 32, relu ----
        #pragma unroll
        for (int o = 0; o < 32; o++) A[o] = sb1[o];
        feed<32>(x0, sw1 +  0, A);
        feed<32>(x1, sw1 + 32, A);
        feed<32>(x2, sw1 + 64, A);
        {
            const float* wp = sw1 + 96;
            float s = 1.0f;
            #pragma unroll
            for (int j = 0; j < 10; j++) {
                float sn0, cs0, sn1, cs1, sn2, cs2;
                sincosf(s * x0, &sn0, &cs0);
                sincosf(s * x1, &sn1, &cs1);
                sincosf(s * x2, &sn2, &cs2);
                feed<32>(sn0, wp, A); wp += 32;
                feed<32>(sn1, wp, A); wp += 32;
                feed<32>(sn2, wp, A); wp += 32;
                feed<32>(cs0, wp, A); wp += 32;
                feed<32>(cs1, wp, A); wp += 32;
                feed<32>(cs2, wp, A); wp += 32;
                s *= 2.0f;
            }
        }
        #pragma unroll
        for (int o = 0; o < 32; o++) A[o] = fmaxf(A[o], 0.0f);

        // ---- layer 2: 32 -> 33, relu; sigma = out[0] ----
        #pragma unroll
        for (int o = 0; o < 33; o++) B[o] = sb2[o];
        #pragma unroll
        for (int i = 0; i < 32; i++) feed<33>(A[i], sw2 + i * 33, B);
        #pragma unroll
        for (int o = 0; o < 33; o++) B[o] = fmaxf(B[o], 0.0f);
        float sigma = B[0];

        // ---- layer 3: 32 -> 32, linear ----
        #pragma unroll
        for (int o = 0; o < 32; o++) A[o] = sb3[o];
        #pragma unroll
        for (int i = 0; i < 32; i++) feed<32>(B[i + 1], sw3 + i * 32, A);

        // ---- layer 4: [32 | encode(d) 27] -> 32, relu ----
        #pragma unroll
        for (int o = 0; o < 32; o++) B[o] = sb4[o];
        #pragma unroll
        for (int i = 0; i < 32; i++) feed<32>(A[i], sw4 + i * 32, B);
        {
            const float* wp = sw4 + 32 * 32;
            feed<32>(d0, wp, B); wp += 32;
            feed<32>(d1, wp, B); wp += 32;
            feed<32>(d2, wp, B); wp += 32;
            float s = 1.0f;
            #pragma unroll
            for (int j = 0; j < 4; j++) {
                float sn0, cs0, sn1, cs1, sn2, cs2;
                sincosf(s * d0, &sn0, &cs0);
                sincosf(s * d1, &sn1, &cs1);
                sincosf(s * d2, &sn2, &cs2);
                feed<32>(sn0, wp, B); wp += 32;
                feed<32>(sn1, wp, B); wp += 32;
                feed<32>(sn2, wp, B); wp += 32;
                feed<32>(cs0, wp, B); wp += 32;
                feed<32>(cs1, wp, B); wp += 32;
                feed<32>(cs2, wp, B); wp += 32;
                s *= 2.0f;
            }
        }
        #pragma unroll
        for (int o = 0; o < 32; o++) B[o] = fmaxf(B[o], 0.0f);

        // ---- layer 5: 32 -> 3, sigmoid ----
        float r0 = sb5[0], r1 = sb5[1], r2 = sb5[2];
        #pragma unroll
        for (int i = 0; i < 32; i++) {
            float v = B[i];
            r0 = fmaf(v, sw5[i * 3 + 0], r0);
            r1 = fmaf(v, sw5[i * 3 + 1], r1);
            r2 = fmaf(v, sw5[i * 3 + 2], r2);
        }
        r0 = 1.0f / (1.0f + expf(-r0));
        r1 = 1.0f / (1.0f + expf(-r1));
        r2 = 1.0f / (1.0f + expf(-r2));

        if (!mask) { r0 = 0.0f; r1 = 0.0f; r2 = 0.0f; sigma = 0.0f; }

        out[3 * idx + 0] = r0;
        out[3 * idx + 1] = r1;
        out[3 * idx + 2] = r2;
        out[3 * NPTS + idx] = sigma;
    }
}

// ---------------- launch ----------------------------------------------------
extern "C" void kernel_launch(void* const* d_in, const int* in_sizes, int n_in,
                              void* d_out, int out_size) {
    const float* x  = (const float*)d_in[0];
    const float* dd = (const float*)d_in[1];
    const float* w1 = (const float*)d_in[2];
    const float* b1 = (const float*)d_in[3];
    const float* w2 = (const float*)d_in[4];
    const float* b2 = (const float*)d_in[5];
    const float* w3 = (const float*)d_in[6];
    const float* b3 = (const float*)d_in[7];
    const float* w4 = (const float*)d_in[8];
    const float* b4 = (const float*)d_in[9];
    const float* w5 = (const float*)d_in[10];
    const float* b5 = (const float*)d_in[11];
    float* out = (float*)d_out;

    k_zero<<<(NC + 255) / 256, 256>>>();
    k_hist<<<NPTS / 256, 256>>>(x);
    k_scan<<<1, 1024>>>();
    k_scatter<<<NPTS / 256, 256>>>();
    k_mlp<<<NC, 64>>>(x, dd, w1, b1, w2, b2, w3, b3, w4, b4, w5, b5, out);
}

// round 2
// speedup vs baseline: 1.5310x; 1.5310x over previous
#include <cuda_runtime.h>
#include <math.h>

#define NPTS 131072
#define NC 4096

// ---------------- scratch (device globals: zero-initialized at load) -------
__device__ int g_cell_of[NPTS];
__device__ int g_sorted[NPTS];
__device__ int g_count[NC];      // zeroed by k_scan after reading (and statically)
__device__ int g_start[NC + 1];
__device__ int g_cursor[NC];     // zeroed by k_mlp for next call (and statically)

__device__ __forceinline__ int cell_coord(float v) {
    // match jnp: clip((x / (SCALE/N) + N/2).astype(int32), 0, N-1); trunc toward 0
    float f = v / 0.1875f + 8.0f;
    int c = (int)f;
    if (c < 0) c = 0;
    if (c > 15) c = 15;
    return c;
}

// ---------------- pass 1: cell index + histogram ----------------------------
__global__ void k_hist(const float* __restrict__ x) {
    int p = blockIdx.x * blockDim.x + threadIdx.x;
    if (p >= NPTS) return;
    int c0 = cell_coord(x[3 * p + 0]);
    int c1 = cell_coord(x[3 * p + 1]);
    int c2 = cell_coord(x[3 * p + 2]);
    int cell = (c0 * 16 + c1) * 16 + c2;
    g_cell_of[p] = cell;
    atomicAdd(&g_count[cell], 1);
}

// ---------------- pass 2: exclusive scan + reset counts (1 block) ----------
__global__ void k_scan() {
    __shared__ int s[1024];
    int t = threadIdx.x;           // launched with 1024 threads
    int b = t * 4;
    int c0 = g_count[b + 0];
    int c1 = g_count[b + 1];
    int c2 = g_count[b + 2];
    int c3 = g_count[b + 3];
    // reset for the next kernel_launch invocation
    g_count[b + 0] = 0; g_count[b + 1] = 0; g_count[b + 2] = 0; g_count[b + 3] = 0;
    int sum = c0 + c1 + c2 + c3;
    s[t] = sum;
    __syncthreads();
    #pragma unroll
    for (int off = 1; off < 1024; off <<= 1) {
        int v = (t >= off) ? s[t - off] : 0;
        __syncthreads();
        s[t] += v;
        __syncthreads();
    }
    int excl = s[t] - sum;
    g_start[b + 0] = excl;
    g_start[b + 1] = excl + c0;
    g_start[b + 2] = excl + c0 + c1;
    g_start[b + 3] = excl + c0 + c1 + c2;
    if (t == 1023) g_start[NC] = s[1023];
}

// ---------------- pass 3: scatter point indices into cell buckets ----------
__global__ void k_scatter() {
    int p = blockIdx.x * blockDim.x + threadIdx.x;
    if (p >= NPTS) return;
    int cell = g_cell_of[p];
    int pos = g_start[cell] + atomicAdd(&g_cursor[cell], 1);
    g_sorted[pos] = p;
}

// ---------------- fast sincos: Cody-Waite reduction + MUFU ------------------
__device__ __forceinline__ void fsincos(float a, float& sn, float& cs) {
    float k = rintf(a * 0.15915493667125702f);           // a / (2*pi)
    float r = fmaf(k, -6.2831854820251465f, a);          // a - k*2pi_hi
    r = fmaf(k, 1.7484556000744487e-7f, r);              // - k*2pi_lo (lo is negative)
    sn = __sinf(r);
    cs = __cosf(r);
}

// ---------------- pass 4: per-cell MLP, weights in shared, 1 warp/cell -----
template <int NO>
__device__ __forceinline__ void feed(float v, const float* __restrict__ w,
                                     float* acc) {
    #pragma unroll
    for (int o = 0; o < NO; o++) acc[o] = fmaf(v, w[o], acc[o]);
}

__global__ void __launch_bounds__(32, 9) k_mlp(
    const float* __restrict__ x, const float* __restrict__ d,
    const float* __restrict__ w1, const float* __restrict__ b1,
    const float* __restrict__ w2, const float* __restrict__ b2,
    const float* __restrict__ w3, const float* __restrict__ b3,
    const float* __restrict__ w4, const float* __restrict__ b4,
    const float* __restrict__ w5, const float* __restrict__ b5,
    float* __restrict__ out)
{
    int cell = blockIdx.x;
    int tid = threadIdx.x;

    if (tid == 0) g_cursor[cell] = 0;   // reset for next invocation

    int start = g_start[cell];
    int cnt = g_start[cell + 1] - start;
    if (cnt == 0) return;

    __shared__ __align__(16) float sw1[2016];      // 63 x 32 (rows of 32, aligned)
    __shared__ __align__(16) float sb1[32];
    __shared__ __align__(16) float sw2[32 * 36];   // 32 x 33, rows padded to 36
    __shared__ __align__(16) float sb2[36];
    __shared__ __align__(16) float sw3[1024];      // 32 x 32
    __shared__ __align__(16) float sb3[32];
    __shared__ __align__(16) float sw4[1888];      // 59 x 32
    __shared__ __align__(16) float sb4[32];
    __shared__ __align__(16) float sw5[32 * 4];    // 32 x 3 padded to stride 4
    __shared__ __align__(16) float sb5[4];

    {
        const size_t c = (size_t)cell;
        const float4* w1v = (const float4*)(w1 + c * 2016);
        const float4* w3v = (const float4*)(w3 + c * 1024);
        const float4* w4v = (const float4*)(w4 + c * 1888);
        #pragma unroll
        for (int i = 0; i < 16; i++) ((float4*)sw1)[tid + 32 * i] = w1v[tid + 32 * i];
        #pragma unroll
        for (int i = 0; i < 8; i++)  ((float4*)sw3)[tid + 32 * i] = w3v[tid + 32 * i];
        #pragma unroll
        for (int i = 0; i < 14; i++) ((float4*)sw4)[tid + 32 * i] = w4v[tid + 32 * i];
        if (tid < 472 - 32 * 14)     ((float4*)sw4)[tid + 32 * 14] = w4v[tid + 32 * 14];
        // w2 with row padding 33 -> 36
        for (int i = tid; i < 1056; i += 32) {
            int r = i / 33, cc = i - r * 33;
            sw2[r * 36 + cc] = w2[c * 1056 + i];
        }
        // w5 with row padding 3 -> 4
        for (int i = tid; i < 96; i += 32) {
            int r = i / 3, cc = i - r * 3;
            sw5[r * 4 + cc] = w5[c * 96 + i];
        }
        sb1[tid] = b1[c * 32 + tid];
        sb3[tid] = b3[c * 32 + tid];
        sb4[tid] = b4[c * 32 + tid];
        sb2[tid] = b2[c * 33 + tid];
        if (tid == 0) sb2[32] = b2[c * 33 + 32];
        if (tid < 3) sb5[tid] = b5[c * 3 + tid];
    }
    __syncwarp();

    for (int q = tid; q < cnt; q += 32) {
        int idx = g_sorted[start + q];
        float x0 = x[3 * idx + 0], x1 = x[3 * idx + 1], x2 = x[3 * idx + 2];
        float d0 = d[3 * idx + 0], d1 = d[3 * idx + 1], d2 = d[3 * idx + 2];
        bool mask = (fabsf(x0) < 1.5f) && (fabsf(x1) < 1.5f) && (fabsf(x2) < 1.5f);

        float A[33], B[33];

        // ---- layer 1: encode(x) [63] -> 32, relu ----
        #pragma unroll
        for (int o = 0; o < 32; o++) A[o] = sb1[o];
        feed<32>(x0, sw1 +  0, A);
        feed<32>(x1, sw1 + 32, A);
        feed<32>(x2, sw1 + 64, A);
        {
            const float* wp = sw1 + 96;
            float s = 1.0f;
            #pragma unroll
            for (int j = 0; j < 10; j++) {
                float sn0, cs0, sn1, cs1, sn2, cs2;
                fsincos(s * x0, sn0, cs0);
                fsincos(s * x1, sn1, cs1);
                fsincos(s * x2, sn2, cs2);
                feed<32>(sn0, wp, A); wp += 32;
                feed<32>(sn1, wp, A); wp += 32;
                feed<32>(sn2, wp, A); wp += 32;
                feed<32>(cs0, wp, A); wp += 32;
                feed<32>(cs1, wp, A); wp += 32;
                feed<32>(cs2, wp, A); wp += 32;
                s *= 2.0f;
            }
        }
        #pragma unroll
        for (int o = 0; o < 32; o++) A[o] = fmaxf(A[o], 0.0f);

        // ---- layer 2: 32 -> 33, relu; sigma = out[0] ----
        #pragma unroll
        for (int o = 0; o < 33; o++) B[o] = sb2[o];
        #pragma unroll
        for (int i = 0; i < 32; i++) feed<33>(A[i], sw2 + i * 36, B);
        #pragma unroll
        for (int o = 0; o < 33; o++) B[o] = fmaxf(B[o], 0.0f);
        float sigma = B[0];

        // ---- layer 3: 32 -> 32, linear ----
        #pragma unroll
        for (int o = 0; o < 32; o++) A[o] = sb3[o];
        #pragma unroll
        for (int i = 0; i < 32; i++) feed<32>(B[i + 1], sw3 + i * 32, A);

        // ---- layer 4: [32 | encode(d) 27] -> 32, relu ----
        #pragma unroll
        for (int o = 0; o < 32; o++) B[o] = sb4[o];
        #pragma unroll
        for (int i = 0; i < 32; i++) feed<32>(A[i], sw4 + i * 32, B);
        {
            const float* wp = sw4 + 32 * 32;
            feed<32>(d0, wp, B); wp += 32;
            feed<32>(d1, wp, B); wp += 32;
            feed<32>(d2, wp, B); wp += 32;
            float s = 1.0f;
            #pragma unroll
            for (int j = 0; j < 4; j++) {
                float sn0, cs0, sn1, cs1, sn2, cs2;
                fsincos(s * d0, sn0, cs0);
                fsincos(s * d1, sn1, cs1);
                fsincos(s * d2, sn2, cs2);
                feed<32>(sn0, wp, B); wp += 32;
                feed<32>(sn1, wp, B); wp += 32;
                feed<32>(sn2, wp, B); wp += 32;
                feed<32>(cs0, wp, B); wp += 32;
                feed<32>(cs1, wp, B); wp += 32;
                feed<32>(cs2, wp, B); wp += 32;
                s *= 2.0f;
            }
        }
        #pragma unroll
        for (int o = 0; o < 32; o++) B[o] = fmaxf(B[o], 0.0f);

        // ---- layer 5: 32 -> 3, sigmoid ----
        float r0 = sb5[0], r1 = sb5[1], r2 = sb5[2];
        #pragma unroll
        for (int i = 0; i < 32; i++) {
            float v = B[i];
            r0 = fmaf(v, sw5[i * 4 + 0], r0);
            r1 = fmaf(v, sw5[i * 4 + 1], r1);
            r2 = fmaf(v, sw5[i * 4 + 2], r2);
        }
        r0 = 1.0f / (1.0f + __expf(-r0));
        r1 = 1.0f / (1.0f + __expf(-r1));
        r2 = 1.0f / (1.0f + __expf(-r2));

        if (!mask) { r0 = 0.0f; r1 = 0.0f; r2 = 0.0f; sigma = 0.0f; }

        out[3 * idx + 0] = r0;
        out[3 * idx + 1] = r1;
        out[3 * idx + 2] = r2;
        out[3 * NPTS + idx] = sigma;
    }
}

// ---------------- launch ----------------------------------------------------
extern "C" void kernel_launch(void* const* d_in, const int* in_sizes, int n_in,
                              void* d_out, int out_size) {
    const float* x  = (const float*)d_in[0];
    const float* dd = (const float*)d_in[1];
    const float* w1 = (const float*)d_in[2];
    const float* b1 = (const float*)d_in[3];
    const float* w2 = (const float*)d_in[4];
    const float* b2 = (const float*)d_in[5];
    const float* w3 = (const float*)d_in[6];
    const float* b3 = (const float*)d_in[7];
    const float* w4 = (const float*)d_in[8];
    const float* b4 = (const float*)d_in[9];
    const float* w5 = (const float*)d_in[10];
    const float* b5 = (const float*)d_in[11];
    float* out = (float*)d_out;

    k_hist<<<NPTS / 256, 256>>>(x);
    k_scan<<<1, 1024>>>();
    k_scatter<<<NPTS / 256, 256>>>();
    k_mlp<<<NC, 32>>>(x, dd, w1, b1, w2, b2, w3, b3, w4, b4, w5, b5, out);
}